// round 3
// baseline (speedup 1.0000x reference)
#include <cuda_runtime.h>
#include <math.h>

#define N_NODES 100000
#define N_EDGES 1600000
#define IN_F 128
#define HID 128
#define NC 10
#define NCP 12
#define SCAN_T 1024
#define CHUNK 98   // ceil(N_NODES / SCAN_T)

// ---------------- scratch (static device globals; no allocs) ----------------
__device__ int   g_is64;
__device__ int   g_src   [N_EDGES];
__device__ int   g_dst   [N_EDGES];
__device__ int   g_deg   [N_NODES];
__device__ int   g_rowptr[N_NODES];
__device__ int   g_cursor[N_NODES];
__device__ float g_dinv  [N_NODES];
__device__ int   g_col   [N_EDGES];
__device__ __align__(16) float g_h1[N_NODES * HID];   // X @ W1
__device__ __align__(16) float g_a1[N_NODES * HID];   // relu(aggregate + b1)
__device__ __align__(16) float g_h2[N_NODES * NCP];   // a1 @ W2 (padded rows)

// ---------------- dtype sniff: int64 edge_index has zero high words ----------------
__global__ void detect_dtype(const int* __restrict__ raw) {
    if (threadIdx.x == 0 && blockIdx.x == 0) {
        int any = 0;
        #pragma unroll
        for (int k = 0; k < 8; k++) any |= raw[2 * k + 1];
        g_is64 = (any == 0) ? 1 : 0;
    }
}

// ---------------- zero degree ----------------
__global__ void zero_deg() {
    int i = blockIdx.x * blockDim.x + threadIdx.x;
    if (i < N_NODES) g_deg[i] = 0;
}

// ---------------- convert edges to int32 + degree count ----------------
__global__ void convert_edges(const int* __restrict__ raw) {
    int e = blockIdx.x * blockDim.x + threadIdx.x;
    if (e >= N_EDGES) return;
    int s, d;
    if (g_is64) {               // little-endian int64: take low words
        s = raw[2 * e];
        d = raw[2 * (N_EDGES + e)];
    } else {                    // int32
        s = raw[e];
        d = raw[N_EDGES + e];
    }
    g_src[e] = s;
    g_dst[e] = d;
    atomicAdd(&g_deg[d], 1);
}

// ---------------- single-block exclusive scan + dinv ----------------
__global__ void __launch_bounds__(SCAN_T) scan_dinv() {
    __shared__ int wsum[32];
    int t = threadIdx.x;
    int lane = t & 31, warp = t >> 5;
    int lo = t * CHUNK;
    int hi = lo + CHUNK; if (hi > N_NODES) hi = N_NODES;

    int s = 0;
    for (int i = lo; i < hi; i++) s += g_deg[i];

    int v = s;
    #pragma unroll
    for (int o = 1; o < 32; o <<= 1) {
        int n = __shfl_up_sync(0xFFFFFFFFu, v, o);
        if (lane >= o) v += n;
    }
    if (lane == 31) wsum[warp] = v;
    __syncthreads();
    if (warp == 0) {
        int w = wsum[lane];
        #pragma unroll
        for (int o = 1; o < 32; o <<= 1) {
            int n = __shfl_up_sync(0xFFFFFFFFu, w, o);
            if (lane >= o) w += n;
        }
        wsum[lane] = w;
    }
    __syncthreads();

    int base = (v - s) + (warp ? wsum[warp - 1] : 0);
    int run = base;
    for (int i = lo; i < hi; i++) {
        int d = g_deg[i];
        g_rowptr[i] = run;
        g_cursor[i] = run;
        g_dinv[i]   = rsqrtf((float)d + 1.0f);   // +1 = self loop
        run += d;
    }
}

// ---------------- CSR fill ----------------
__global__ void fill_csr() {
    int e = blockIdx.x * blockDim.x + threadIdx.x;
    if (e < N_EDGES) {
        int p = atomicAdd(&g_cursor[g_dst[e]], 1);
        g_col[p] = g_src[e];
    }
}

// ---------------- mm1: h1 = X @ W1 ----------------
__global__ void __launch_bounds__(128) mm1(const float* __restrict__ x,
                                           const float* __restrict__ W) {
    __shared__ float xs[32][IN_F];
    const int tx = threadIdx.x & 31;
    const int ty = threadIdx.x >> 5;
    const int row0 = blockIdx.x * 32;

    const float4* xv = (const float4*)(x + (size_t)row0 * IN_F);
    float4* sv = (float4*)&xs[0][0];
    #pragma unroll
    for (int i = 0; i < 8; i++) sv[threadIdx.x + i * 128] = xv[threadIdx.x + i * 128];
    __syncthreads();

    float acc[8][4];
    #pragma unroll
    for (int r = 0; r < 8; r++)
        #pragma unroll
        for (int c = 0; c < 4; c++) acc[r][c] = 0.f;

    const float4* Wv = (const float4*)W;
    #pragma unroll 4
    for (int k = 0; k < IN_F; k++) {
        float4 w = Wv[k * 32 + tx];
        #pragma unroll
        for (int r = 0; r < 8; r++) {
            float a = xs[ty * 8 + r][k];
            acc[r][0] = fmaf(a, w.x, acc[r][0]);
            acc[r][1] = fmaf(a, w.y, acc[r][1]);
            acc[r][2] = fmaf(a, w.z, acc[r][2]);
            acc[r][3] = fmaf(a, w.w, acc[r][3]);
        }
    }
    #pragma unroll
    for (int r = 0; r < 8; r++) {
        int row = row0 + ty * 8 + r;
        ((float4*)(g_h1 + (size_t)row * HID))[tx] =
            make_float4(acc[r][0], acc[r][1], acc[r][2], acc[r][3]);
    }
}

// ---------------- gather1: a1[i] = relu(sum_j norm*h1[src_j] + self + b1) ----------------
__global__ void __launch_bounds__(256) gather1(const float* __restrict__ b1) {
    int warp = threadIdx.x >> 5, lane = threadIdx.x & 31;
    int i = blockIdx.x * 8 + warp;
    if (i >= N_NODES) return;

    float dd = g_dinv[i];
    int start = g_rowptr[i], cnt = g_deg[i];

    float4 h = ((const float4*)(g_h1 + (size_t)i * HID))[lane];
    float selfs = dd * dd;
    float4 acc = make_float4(h.x * selfs, h.y * selfs, h.z * selfs, h.w * selfs);

    for (int base = 0; base < cnt; base += 32) {
        int j = base + lane;
        int cid = 0; float nv = 0.f;
        if (j < cnt) { cid = g_col[start + j]; nv = g_dinv[cid]; }
        int m = cnt - base; if (m > 32) m = 32;
        for (int k = 0; k < m; k++) {
            int   s   = __shfl_sync(0xFFFFFFFFu, cid, k);
            float nrm = __shfl_sync(0xFFFFFFFFu, nv,  k) * dd;
            float4 v = ((const float4*)(g_h1 + (size_t)s * HID))[lane];
            acc.x = fmaf(v.x, nrm, acc.x);
            acc.y = fmaf(v.y, nrm, acc.y);
            acc.z = fmaf(v.z, nrm, acc.z);
            acc.w = fmaf(v.w, nrm, acc.w);
        }
    }
    float4 b = ((const float4*)b1)[lane];
    acc.x = fmaxf(acc.x + b.x, 0.f);
    acc.y = fmaxf(acc.y + b.y, 0.f);
    acc.z = fmaxf(acc.z + b.z, 0.f);
    acc.w = fmaxf(acc.w + b.w, 0.f);
    ((float4*)(g_a1 + (size_t)i * HID))[lane] = acc;
}

// ---------------- mm2: h2 = a1 @ W2 (warp per row) ----------------
__global__ void __launch_bounds__(256) mm2(const float* __restrict__ W2) {
    __shared__ float Ws[HID * NC];
    for (int i = threadIdx.x; i < HID * NC; i += 256) Ws[i] = W2[i];
    __syncthreads();
    int warp = threadIdx.x >> 5, lane = threadIdx.x & 31;
    int row = blockIdx.x * 8 + warp;
    if (row >= N_NODES) return;

    float acc[NC];
    #pragma unroll
    for (int c = 0; c < NC; c++) acc[c] = 0.f;
    const float* a = g_a1 + (size_t)row * HID;
    #pragma unroll
    for (int kk = 0; kk < 4; kk++) {
        int k = kk * 32 + lane;
        float av = a[k];
        #pragma unroll
        for (int c = 0; c < NC; c++) acc[c] = fmaf(av, Ws[k * NC + c], acc[c]);
    }
    #pragma unroll
    for (int c = 0; c < NC; c++)
        #pragma unroll
        for (int off = 16; off; off >>= 1)
            acc[c] += __shfl_xor_sync(0xFFFFFFFFu, acc[c], off);
    if (lane == 0) {
        float* o = g_h2 + (size_t)row * NCP;
        #pragma unroll
        for (int c = 0; c < NC; c++) o[c] = acc[c];
    }
}

// ---------------- gather2 + softmax ----------------
__global__ void __launch_bounds__(256) gather2(const float* __restrict__ b2,
                                               float* __restrict__ out) {
    int warp = threadIdx.x >> 5, lane = threadIdx.x & 31;
    int i = blockIdx.x * 8 + warp;
    if (i >= N_NODES) return;

    float dd = g_dinv[i];
    int start = g_rowptr[i], cnt = g_deg[i];

    float acc = 0.f;
    if (lane < NC) acc = g_h2[(size_t)i * NCP + lane] * dd * dd;

    for (int base = 0; base < cnt; base += 32) {
        int j = base + lane;
        int cid = 0; float nv = 0.f;
        if (j < cnt) { cid = g_col[start + j]; nv = g_dinv[cid]; }
        int m = cnt - base; if (m > 32) m = 32;
        for (int k = 0; k < m; k++) {
            int   s   = __shfl_sync(0xFFFFFFFFu, cid, k);
            float nrm = __shfl_sync(0xFFFFFFFFu, nv,  k) * dd;
            float v = (lane < NC) ? g_h2[(size_t)s * NCP + lane] : 0.f;
            acc = fmaf(v, nrm, acc);
        }
    }

    float val = (lane < NC) ? acc + b2[lane] : -INFINITY;
    float mx = val;
    #pragma unroll
    for (int o = 16; o; o >>= 1) mx = fmaxf(mx, __shfl_xor_sync(0xFFFFFFFFu, mx, o));
    float e = (lane < NC) ? expf(val - mx) : 0.f;
    float ssum = e;
    #pragma unroll
    for (int o = 16; o; o >>= 1) ssum += __shfl_xor_sync(0xFFFFFFFFu, ssum, o);
    if (lane < NC) out[(size_t)i * NC + lane] = e / ssum;
}

// ---------------- launch ----------------
extern "C" void kernel_launch(void* const* d_in, const int* in_sizes, int n_in,
                              void* d_out, int out_size) {
    const float* x  = (const float*)d_in[0];
    const int*   ei = (const int*)d_in[1];   // int32 or int64 (sniffed on device)
    const float* W1 = (const float*)d_in[2];
    const float* b1 = (const float*)d_in[3];
    const float* W2 = (const float*)d_in[4];
    const float* b2 = (const float*)d_in[5];
    float* out = (float*)d_out;

    detect_dtype<<<1, 32>>>(ei);
    zero_deg<<<(N_NODES + 255) / 256, 256>>>();
    convert_edges<<<(N_EDGES + 255) / 256, 256>>>(ei);
    scan_dinv<<<1, SCAN_T>>>();
    fill_csr<<<(N_EDGES + 255) / 256, 256>>>();

    mm1<<<N_NODES / 32, 128>>>(x, W1);            // 100000 % 32 == 0
    gather1<<<N_NODES / 8, 256>>>(b1);            // 100000 % 8 == 0
    mm2<<<N_NODES / 8, 256>>>(W2);
    gather2<<<N_NODES / 8, 256>>>(b2, out);
}

// round 4
// speedup vs baseline: 1.6880x; 1.6880x over previous
#include <cuda_runtime.h>
#include <math.h>

#define N_NODES 100000
#define N_EDGES 1600000
#define IN_F 128
#define HID 128
#define NC 10
#define NCP 12
#define SCAN_B 98          // ceil(100000 / 1024)
#define SCAN_T 1024

// ---------------- scratch (static device globals; no allocs) ----------------
__device__ int   g_is64;
__device__ int   g_src   [N_EDGES];
__device__ int   g_dst   [N_EDGES];
__device__ int   g_deg   [N_NODES];
__device__ int   g_rowptr[N_NODES];
__device__ int   g_cursor[N_NODES];
__device__ float g_dinv  [N_NODES];
__device__ int   g_col   [N_EDGES];
__device__ int   g_bsum  [SCAN_B];
__device__ int   g_boff  [SCAN_B];
__device__ __align__(16) float g_h1[N_NODES * HID];   // X @ W1
__device__ __align__(16) float g_a1[N_NODES * HID];   // relu(aggregate + b1)
__device__ __align__(16) float g_h2[N_NODES * NCP];   // a1 @ W2 (padded rows)

// ---------------- dtype sniff: int64 edge_index has zero high words ----------------
__global__ void detect_dtype(const int* __restrict__ raw) {
    if (threadIdx.x == 0 && blockIdx.x == 0) {
        int any = 0;
        #pragma unroll
        for (int k = 0; k < 8; k++) any |= raw[2 * k + 1];
        g_is64 = (any == 0) ? 1 : 0;
    }
}

// ---------------- zero degree ----------------
__global__ void zero_deg() {
    int i = blockIdx.x * blockDim.x + threadIdx.x;
    if (i < N_NODES) g_deg[i] = 0;
}

// ---------------- convert edges to int32 + degree count ----------------
__global__ void convert_edges(const int* __restrict__ raw) {
    int e = blockIdx.x * blockDim.x + threadIdx.x;
    if (e >= N_EDGES) return;
    int s, d;
    if (g_is64) {               // little-endian int64: take low words
        s = raw[2 * e];
        d = raw[2 * (N_EDGES + e)];
    } else {                    // int32
        s = raw[e];
        d = raw[N_EDGES + e];
    }
    g_src[e] = s;
    g_dst[e] = d;
    atomicAdd(&g_deg[d], 1);
}

// ---------------- parallel scan, phase A: per-block reduce ----------------
__global__ void __launch_bounds__(SCAN_T) scanA() {
    __shared__ int wsum[32];
    int i = blockIdx.x * SCAN_T + threadIdx.x;
    int lane = threadIdx.x & 31, warp = threadIdx.x >> 5;
    int d = (i < N_NODES) ? g_deg[i] : 0;
    int v = d;
    #pragma unroll
    for (int o = 16; o; o >>= 1) v += __shfl_xor_sync(0xFFFFFFFFu, v, o);
    if (lane == 0) wsum[warp] = v;
    __syncthreads();
    if (warp == 0) {
        int w = (lane < 32) ? wsum[lane] : 0;
        #pragma unroll
        for (int o = 16; o; o >>= 1) w += __shfl_xor_sync(0xFFFFFFFFu, w, o);
        if (lane == 0) g_bsum[blockIdx.x] = w;
    }
}

// ---------------- phase B: scan the 98 block sums (one block) ----------------
__global__ void __launch_bounds__(128) scanB() {
    __shared__ int wsum[4];
    int t = threadIdx.x;
    int lane = t & 31, warp = t >> 5;
    int s = (t < SCAN_B) ? g_bsum[t] : 0;
    int v = s;
    #pragma unroll
    for (int o = 1; o < 32; o <<= 1) {
        int n = __shfl_up_sync(0xFFFFFFFFu, v, o);
        if (lane >= o) v += n;
    }
    if (lane == 31) wsum[warp] = v;
    __syncthreads();
    int off = 0;
    for (int w = 0; w < warp; w++) off += wsum[w];
    if (t < SCAN_B) g_boff[t] = off + v - s;   // exclusive
}

// ---------------- phase C: per-block scan + offsets, write rowptr/cursor/dinv ----------------
__global__ void __launch_bounds__(SCAN_T) scanC() {
    __shared__ int wsum[32];
    int i = blockIdx.x * SCAN_T + threadIdx.x;
    int lane = threadIdx.x & 31, warp = threadIdx.x >> 5;
    int d = (i < N_NODES) ? g_deg[i] : 0;
    int v = d;
    #pragma unroll
    for (int o = 1; o < 32; o <<= 1) {
        int n = __shfl_up_sync(0xFFFFFFFFu, v, o);
        if (lane >= o) v += n;
    }
    if (lane == 31) wsum[warp] = v;
    __syncthreads();
    if (warp == 0) {
        int w = wsum[lane];
        #pragma unroll
        for (int o = 1; o < 32; o <<= 1) {
            int n = __shfl_up_sync(0xFFFFFFFFu, w, o);
            if (lane >= o) w += n;
        }
        wsum[lane] = w;
    }
    __syncthreads();
    if (i < N_NODES) {
        int p = g_boff[blockIdx.x] + (warp ? wsum[warp - 1] : 0) + (v - d);
        g_rowptr[i] = p;
        g_cursor[i] = p;
        g_dinv[i]   = rsqrtf((float)d + 1.0f);   // +1 = self loop
    }
}

// ---------------- CSR fill ----------------
__global__ void fill_csr() {
    int e = blockIdx.x * blockDim.x + threadIdx.x;
    if (e < N_EDGES) {
        int p = atomicAdd(&g_cursor[g_dst[e]], 1);
        g_col[p] = g_src[e];
    }
}

// ---------------- mm1: h1 = X @ W1 ----------------
__global__ void __launch_bounds__(128) mm1(const float* __restrict__ x,
                                           const float* __restrict__ W) {
    __shared__ float xs[32][IN_F];
    const int tx = threadIdx.x & 31;
    const int ty = threadIdx.x >> 5;
    const int row0 = blockIdx.x * 32;

    const float4* xv = (const float4*)(x + (size_t)row0 * IN_F);
    float4* sv = (float4*)&xs[0][0];
    #pragma unroll
    for (int i = 0; i < 8; i++) sv[threadIdx.x + i * 128] = xv[threadIdx.x + i * 128];
    __syncthreads();

    float acc[8][4];
    #pragma unroll
    for (int r = 0; r < 8; r++)
        #pragma unroll
        for (int c = 0; c < 4; c++) acc[r][c] = 0.f;

    const float4* Wv = (const float4*)W;
    #pragma unroll 4
    for (int k = 0; k < IN_F; k++) {
        float4 w = Wv[k * 32 + tx];
        #pragma unroll
        for (int r = 0; r < 8; r++) {
            float a = xs[ty * 8 + r][k];
            acc[r][0] = fmaf(a, w.x, acc[r][0]);
            acc[r][1] = fmaf(a, w.y, acc[r][1]);
            acc[r][2] = fmaf(a, w.z, acc[r][2]);
            acc[r][3] = fmaf(a, w.w, acc[r][3]);
        }
    }
    #pragma unroll
    for (int r = 0; r < 8; r++) {
        int row = row0 + ty * 8 + r;
        ((float4*)(g_h1 + (size_t)row * HID))[tx] =
            make_float4(acc[r][0], acc[r][1], acc[r][2], acc[r][3]);
    }
}

// ---------------- gather1: a1[i] = relu(sum_j norm*h1[src_j] + self + b1) ----------------
__global__ void __launch_bounds__(256) gather1(const float* __restrict__ b1) {
    int warp = threadIdx.x >> 5, lane = threadIdx.x & 31;
    int i = blockIdx.x * 8 + warp;
    if (i >= N_NODES) return;

    float dd = g_dinv[i];
    int start = g_rowptr[i], cnt = g_deg[i];

    float4 h = ((const float4*)(g_h1 + (size_t)i * HID))[lane];
    float selfs = dd * dd;
    float4 acc = make_float4(h.x * selfs, h.y * selfs, h.z * selfs, h.w * selfs);

    for (int base = 0; base < cnt; base += 32) {
        int j = base + lane;
        int cid = 0; float nv = 0.f;
        if (j < cnt) { cid = g_col[start + j]; nv = g_dinv[cid]; }
        int m = cnt - base; if (m > 32) m = 32;
        for (int k = 0; k < m; k++) {
            int   s   = __shfl_sync(0xFFFFFFFFu, cid, k);
            float nrm = __shfl_sync(0xFFFFFFFFu, nv,  k) * dd;
            float4 v = ((const float4*)(g_h1 + (size_t)s * HID))[lane];
            acc.x = fmaf(v.x, nrm, acc.x);
            acc.y = fmaf(v.y, nrm, acc.y);
            acc.z = fmaf(v.z, nrm, acc.z);
            acc.w = fmaf(v.w, nrm, acc.w);
        }
    }
    float4 b = ((const float4*)b1)[lane];
    acc.x = fmaxf(acc.x + b.x, 0.f);
    acc.y = fmaxf(acc.y + b.y, 0.f);
    acc.z = fmaxf(acc.z + b.z, 0.f);
    acc.w = fmaxf(acc.w + b.w, 0.f);
    ((float4*)(g_a1 + (size_t)i * HID))[lane] = acc;
}

// ---------------- mm2: h2 = a1 @ W2 (warp per row) ----------------
__global__ void __launch_bounds__(256) mm2(const float* __restrict__ W2) {
    __shared__ float Ws[HID * NC];
    for (int i = threadIdx.x; i < HID * NC; i += 256) Ws[i] = W2[i];
    __syncthreads();
    int warp = threadIdx.x >> 5, lane = threadIdx.x & 31;
    int row = blockIdx.x * 8 + warp;
    if (row >= N_NODES) return;

    float acc[NC];
    #pragma unroll
    for (int c = 0; c < NC; c++) acc[c] = 0.f;
    const float* a = g_a1 + (size_t)row * HID;
    #pragma unroll
    for (int kk = 0; kk < 4; kk++) {
        int k = kk * 32 + lane;
        float av = a[k];
        #pragma unroll
        for (int c = 0; c < NC; c++) acc[c] = fmaf(av, Ws[k * NC + c], acc[c]);
    }
    #pragma unroll
    for (int c = 0; c < NC; c++)
        #pragma unroll
        for (int off = 16; off; off >>= 1)
            acc[c] += __shfl_xor_sync(0xFFFFFFFFu, acc[c], off);
    if (lane == 0) {
        float* o = g_h2 + (size_t)row * NCP;
        #pragma unroll
        for (int c = 0; c < NC; c++) o[c] = acc[c];
    }
}

// ---------------- gather2 + softmax ----------------
__global__ void __launch_bounds__(256) gather2(const float* __restrict__ b2,
                                               float* __restrict__ out) {
    int warp = threadIdx.x >> 5, lane = threadIdx.x & 31;
    int i = blockIdx.x * 8 + warp;
    if (i >= N_NODES) return;

    float dd = g_dinv[i];
    int start = g_rowptr[i], cnt = g_deg[i];

    float acc = 0.f;
    if (lane < NC) acc = g_h2[(size_t)i * NCP + lane] * dd * dd;

    for (int base = 0; base < cnt; base += 32) {
        int j = base + lane;
        int cid = 0; float nv = 0.f;
        if (j < cnt) { cid = g_col[start + j]; nv = g_dinv[cid]; }
        int m = cnt - base; if (m > 32) m = 32;
        for (int k = 0; k < m; k++) {
            int   s   = __shfl_sync(0xFFFFFFFFu, cid, k);
            float nrm = __shfl_sync(0xFFFFFFFFu, nv,  k) * dd;
            float v = (lane < NC) ? g_h2[(size_t)s * NCP + lane] : 0.f;
            acc = fmaf(v, nrm, acc);
        }
    }

    float val = (lane < NC) ? acc + b2[lane] : -INFINITY;
    float mx = val;
    #pragma unroll
    for (int o = 16; o; o >>= 1) mx = fmaxf(mx, __shfl_xor_sync(0xFFFFFFFFu, mx, o));
    float e = (lane < NC) ? expf(val - mx) : 0.f;
    float ssum = e;
    #pragma unroll
    for (int o = 16; o; o >>= 1) ssum += __shfl_xor_sync(0xFFFFFFFFu, ssum, o);
    if (lane < NC) out[(size_t)i * NC + lane] = e / ssum;
}

// ---------------- launch ----------------
extern "C" void kernel_launch(void* const* d_in, const int* in_sizes, int n_in,
                              void* d_out, int out_size) {
    const float* x  = (const float*)d_in[0];
    const int*   ei = (const int*)d_in[1];   // int32 or int64 (sniffed on device)
    const float* W1 = (const float*)d_in[2];
    const float* b1 = (const float*)d_in[3];
    const float* W2 = (const float*)d_in[4];
    const float* b2 = (const float*)d_in[5];
    float* out = (float*)d_out;

    detect_dtype<<<1, 32>>>(ei);
    zero_deg<<<(N_NODES + 255) / 256, 256>>>();
    convert_edges<<<(N_EDGES + 255) / 256, 256>>>(ei);
    scanA<<<SCAN_B, SCAN_T>>>();
    scanB<<<1, 128>>>();
    scanC<<<SCAN_B, SCAN_T>>>();
    fill_csr<<<(N_EDGES + 255) / 256, 256>>>();

    mm1<<<N_NODES / 32, 128>>>(x, W1);            // 100000 % 32 == 0
    gather1<<<N_NODES / 8, 256>>>(b1);            // 100000 % 8 == 0
    mm2<<<N_NODES / 8, 256>>>(W2);
    gather2<<<N_NODES / 8, 256>>>(b2, out);
}